// round 8
// baseline (speedup 1.0000x reference)
#include <cuda_runtime.h>
#include <math.h>

// ---------------- problem constants ----------------
constexpr int kB    = 128;   // batch
constexpr int kH    = 512;   // hidden
constexpr int kCtx  = 365;
constexpr int kPred = 90;
constexpr int kT    = 455;   // total steps
constexpr int kDdyn = 10;
constexpr int kEmb  = 64;
constexpr int kStat = 36;
constexpr int kMlp  = 128;
constexpr int kOut  = 4;
constexpr int kNG   = 2048;  // 4*H gate rows
constexpr int kK0   = 528;   // 512 (h) + 10 (x) + 6 zero pad
constexpr int kK1   = 1024;  // 512 (y0) + 512 (h1)
constexpr int kHid  = 256;   // head hidden (H/2)
constexpr int kM2   = kPred * kB;  // 11520 rows for head GEMMs

// ---------------- device scratch (static; no allocations) ----------------
__device__ float g_W0[kNG * kK0];          // interleaved [Whh0 | Wd | pad]
__device__ float g_W1[kNG * kK1];          // interleaved [Wih1 | Whh1]
__device__ float g_pre0[kB * kNG];         // biases + emb part, interleaved rows
__device__ float g_pre1[kNG];              // biases, interleaved rows
__device__ float g_h0[2 * kB * kH];        // layer0 h, ping-pong
__device__ float g_in1[2 * kB * 2 * kH];   // layer1 input [y0 | h1], ping-pong
__device__ float g_c0[kB * kH];
__device__ float g_c1[kB * kH];
__device__ float g_emb[kB * kEmb];
__device__ float g_mlp1[kB * kMlp];
__device__ float g_Y1[kM2 * kH];           // layer1 outputs over pred steps (t-major)
__device__ float g_hid[kM2 * kHid];        // head hidden

__device__ __forceinline__ float sigm(float x) { return 1.f / (1.f + expf(-x)); }

// ---------------- prep kernels ----------------
__global__ void prep_mlp1(const float* __restrict__ sx, const float* __restrict__ w1,
                          const float* __restrict__ b1) {
    int b = blockIdx.x, m = threadIdx.x;           // grid(128), 128 thr
    float s = b1[m];
    #pragma unroll
    for (int d = 0; d < kStat; d++) s += sx[b * kStat + d] * w1[m * kStat + d];
    g_mlp1[b * kMlp + m] = fmaxf(s, 0.f);
}

__global__ void prep_emb(const float* __restrict__ sx, const float* __restrict__ ew,
                         const float* __restrict__ eb) {
    int b = blockIdx.x, e = threadIdx.x;           // grid(128), 64 thr
    float s = eb[e];
    #pragma unroll
    for (int d = 0; d < kStat; d++) s += sx[b * kStat + d] * ew[e * kStat + d];
    g_emb[b * kEmb + e] = fmaxf(s, 0.f);
}

__global__ void prep_init(const float* __restrict__ w2, const float* __restrict__ b2) {
    int b = blockIdx.x;                            // grid(128, 8), 256 thr
    int r = blockIdx.y * 256 + threadIdx.x;        // r < 2048
    float s = b2[r];
    #pragma unroll 4
    for (int m = 0; m < kMlp; m++) s += g_mlp1[b * kMlp + m] * w2[r * kMlp + m];
    int ss = r >> 10, l = (r >> 9) & 1, h = r & 511;
    if (ss == 0) {                                 // h state
        if (l == 0) g_h0[b * kH + h] = s;                  // buffer 0
        else        g_in1[b * 2 * kH + kH + h] = s;        // buffer 0, h1 half
    } else {                                       // c state
        if (l == 0) g_c0[b * kH + h] = s;
        else        g_c1[b * kH + h] = s;
    }
}

__global__ void prep_pre0(const float* __restrict__ wih0, const float* __restrict__ bih,
                          const float* __restrict__ bhh) {
    int b = blockIdx.x;                            // grid(128, 8), 256 thr
    int n = blockIdx.y * 256 + threadIdx.x;        // interleaved row
    int j = (n & 3) * kH + (n >> 2);               // original row
    float s = bih[j] + bhh[j];
    #pragma unroll 8
    for (int e = 0; e < kEmb; e++)
        s += g_emb[b * kEmb + e] * wih0[j * (kDdyn + kEmb) + kDdyn + e];
    g_pre0[b * kNG + n] = s;
}

__global__ void prep_pre1(const float* __restrict__ bih, const float* __restrict__ bhh) {
    int n = blockIdx.x * 256 + threadIdx.x;        // 8 blocks
    int j = (n & 3) * kH + (n >> 2);
    g_pre1[n] = bih[j] + bhh[j];
}

__global__ void prep_W0(const float* __restrict__ whh0, const float* __restrict__ wih0) {
    int idx = blockIdx.x * 256 + threadIdx.x;      // 4224 blocks, = 2048*528
    int n = idx / kK0, k = idx % kK0;
    int j = (n & 3) * kH + (n >> 2);
    float v;
    if (k < kH)              v = whh0[j * kH + k];
    else if (k < kH + kDdyn) v = wih0[j * (kDdyn + kEmb) + (k - kH)];
    else                     v = 0.f;
    g_W0[idx] = v;
}

__global__ void prep_W1(const float* __restrict__ wih1, const float* __restrict__ whh1) {
    int idx = blockIdx.x * 256 + threadIdx.x;      // 8192 blocks, = 2048*1024
    int n = idx >> 10, k = idx & 1023;
    int j = (n & 3) * kH + (n >> 2);
    g_W1[idx] = (k < kH) ? wih1[j * kH + k] : whh1[j * kH + (k - kH)];
}

// ---------------- fused LSTM step: GEMM (64x32 tile) + gate update ----------------
// grid(2, 64), 128 threads. Gate rows are interleaved (row = unit*4 + gate) so each
// CTA owns 8 complete units x 64 batches and does the c/h update in its epilogue.
template <bool L0>
__global__ void __launch_bounds__(128) lstm_step(const float* __restrict__ xsrc,
                                                 int xstride, int par, int trow) {
    constexpr int Ks = L0 ? kK0 : kK1;
    constexpr int NT = Ks / 16;
    constexpr int Astride = L0 ? kH : 2 * kH;

    const float* __restrict__ W = L0 ? g_W0 : g_W1;
    const float* __restrict__ A = (L0 ? g_h0 : g_in1) + par * kB * Astride;

    __shared__ __align__(16) float As[2][16 * 68];
    __shared__ __align__(16) float Bs[2][16 * 36];
    __shared__ float Gs[64 * 33];

    const int tid = threadIdx.x;
    const int m0 = blockIdx.x * 64;    // batch tile
    const int n0 = blockIdx.y * 32;    // gate-row tile (8 units)
    const int tm = tid & 15, tn = tid >> 4;

    float acc[4][4];
    #pragma unroll
    for (int i = 0; i < 4; i++)
        #pragma unroll
        for (int j = 0; j < 4; j++) acc[i][j] = 0.f;

    float ar[8];
    float4 br;

    auto loadA = [&](int k0) {
        #pragma unroll
        for (int i = 0; i < 2; i++) {
            int li = tid * 2 + i;
            int bb = li >> 2, kf = li & 3;
            int kg = k0 + kf * 4;
            int bg = m0 + bb;
            if constexpr (L0) {
                if (kg < kH) {
                    float4 v = *reinterpret_cast<const float4*>(&A[bg * Astride + kg]);
                    ar[i * 4 + 0] = v.x; ar[i * 4 + 1] = v.y;
                    ar[i * 4 + 2] = v.z; ar[i * 4 + 3] = v.w;
                } else {
                    #pragma unroll
                    for (int j = 0; j < 4; j++) {
                        int kk = kg + j - kH;
                        ar[i * 4 + j] = (kk < kDdyn) ? xsrc[bg * xstride + kk] : 0.f;
                    }
                }
            } else {
                float4 v = *reinterpret_cast<const float4*>(&A[bg * Astride + kg]);
                ar[i * 4 + 0] = v.x; ar[i * 4 + 1] = v.y;
                ar[i * 4 + 2] = v.z; ar[i * 4 + 3] = v.w;
            }
        }
    };
    auto storeA = [&](int buf) {
        #pragma unroll
        for (int i = 0; i < 2; i++) {
            int li = tid * 2 + i;
            int bb = li >> 2, kf = li & 3;
            #pragma unroll
            for (int j = 0; j < 4; j++) As[buf][(kf * 4 + j) * 68 + bb] = ar[i * 4 + j];
        }
    };
    auto loadB = [&](int k0) {
        int n = tid >> 2, kf = tid & 3;
        br = *reinterpret_cast<const float4*>(&W[(n0 + n) * Ks + k0 + kf * 4]);
    };
    auto storeB = [&](int buf) {
        int n = tid >> 2, kf = tid & 3;
        Bs[buf][(kf * 4 + 0) * 36 + n] = br.x;
        Bs[buf][(kf * 4 + 1) * 36 + n] = br.y;
        Bs[buf][(kf * 4 + 2) * 36 + n] = br.z;
        Bs[buf][(kf * 4 + 3) * 36 + n] = br.w;
    };

    loadA(0); loadB(0);
    storeA(0); storeB(0);
    __syncthreads();

    for (int kt = 0; kt < NT; ++kt) {
        int cur = kt & 1;
        if (kt + 1 < NT) { loadA((kt + 1) * 16); loadB((kt + 1) * 16); }
        #pragma unroll
        for (int kk = 0; kk < 16; ++kk) {
            float4 av = *reinterpret_cast<const float4*>(&As[cur][kk * 68 + tm * 4]);
            float4 bv = *reinterpret_cast<const float4*>(&Bs[cur][kk * 36 + tn * 4]);
            acc[0][0] += av.x * bv.x; acc[0][1] += av.x * bv.y;
            acc[0][2] += av.x * bv.z; acc[0][3] += av.x * bv.w;
            acc[1][0] += av.y * bv.x; acc[1][1] += av.y * bv.y;
            acc[1][2] += av.y * bv.z; acc[1][3] += av.y * bv.w;
            acc[2][0] += av.z * bv.x; acc[2][1] += av.z * bv.y;
            acc[2][2] += av.z * bv.z; acc[2][3] += av.z * bv.w;
            acc[3][0] += av.w * bv.x; acc[3][1] += av.w * bv.y;
            acc[3][2] += av.w * bv.z; acc[3][3] += av.w * bv.w;
        }
        if (kt + 1 < NT) { storeA(cur ^ 1); storeB(cur ^ 1); }
        __syncthreads();
    }

    // stage gates tile to SMEM so each thread can grab full (i,f,g,o) quadruples
    #pragma unroll
    for (int i = 0; i < 4; i++)
        #pragma unroll
        for (int j = 0; j < 4; j++)
            Gs[(tm * 4 + i) * 33 + tn * 4 + j] = acc[i][j];
    __syncthreads();

    float* __restrict__ cst = L0 ? g_c0 : g_c1;
    float* __restrict__ hA = L0 ? (g_h0 + (par ^ 1) * kB * kH)            // next-step h0
                                : (g_in1 + (par ^ 1) * kB * 2 * kH + kH); // next-step h1
    float* __restrict__ hB = L0 ? (g_in1 + par * kB * 2 * kH)             // y0 for this step's L1
                                : nullptr;

    for (int p = tid; p < 512; p += 128) {   // 64 batches x 8 units
        int bb = p >> 3, uu = p & 7;
        int bg = m0 + bb;
        int nb = n0 + uu * 4;
        int ug = (n0 >> 2) + uu;
        float p0, p1, p2, p3;
        if constexpr (L0) {
            const float* pr = &g_pre0[bg * kNG + nb];
            p0 = pr[0]; p1 = pr[1]; p2 = pr[2]; p3 = pr[3];
        } else {
            p0 = g_pre1[nb]; p1 = g_pre1[nb + 1]; p2 = g_pre1[nb + 2]; p3 = g_pre1[nb + 3];
        }
        float gi = Gs[bb * 33 + uu * 4 + 0] + p0;
        float gf = Gs[bb * 33 + uu * 4 + 1] + p1;
        float gg = Gs[bb * 33 + uu * 4 + 2] + p2;
        float go = Gs[bb * 33 + uu * 4 + 3] + p3;
        float iv = sigm(gi), fv = sigm(gf), gv = tanhf(gg), ov = sigm(go);
        float c = fv * cst[bg * kH + ug] + iv * gv;
        cst[bg * kH + ug] = c;
        float h = ov * tanhf(c);
        if constexpr (L0) {
            hA[bg * kH + ug] = h;
            hB[bg * 2 * kH + ug] = h;
        } else {
            hA[bg * 2 * kH + ug] = h;
            if (trow >= 0) g_Y1[(trow * kB + bg) * kH + ug] = h;
        }
    }
}

// ---------------- head GEMM 1: (11520 x 512) @ (256 x 512)^T + bias, relu ----------------
__global__ void __launch_bounds__(128) head1_gemm(const float* __restrict__ w1,
                                                  const float* __restrict__ b1) {
    __shared__ __align__(16) float As[2][16 * 68];
    __shared__ __align__(16) float Bs[2][16 * 36];
    const int tid = threadIdx.x;
    const int m0 = blockIdx.x * 64, n0 = blockIdx.y * 32;
    const int tm = tid & 15, tn = tid >> 4;
    constexpr int Ks = kH, NT = Ks / 16;

    float acc[4][4];
    #pragma unroll
    for (int i = 0; i < 4; i++)
        #pragma unroll
        for (int j = 0; j < 4; j++) acc[i][j] = 0.f;

    float ar[8];
    float4 br;

    auto loadA = [&](int k0) {
        #pragma unroll
        for (int i = 0; i < 2; i++) {
            int li = tid * 2 + i;
            int bb = li >> 2, kf = li & 3;
            float4 v = *reinterpret_cast<const float4*>(&g_Y1[(m0 + bb) * kH + k0 + kf * 4]);
            ar[i * 4 + 0] = v.x; ar[i * 4 + 1] = v.y; ar[i * 4 + 2] = v.z; ar[i * 4 + 3] = v.w;
        }
    };
    auto storeA = [&](int buf) {
        #pragma unroll
        for (int i = 0; i < 2; i++) {
            int li = tid * 2 + i;
            int bb = li >> 2, kf = li & 3;
            #pragma unroll
            for (int j = 0; j < 4; j++) As[buf][(kf * 4 + j) * 68 + bb] = ar[i * 4 + j];
        }
    };
    auto loadB = [&](int k0) {
        int n = tid >> 2, kf = tid & 3;
        br = *reinterpret_cast<const float4*>(&w1[(n0 + n) * Ks + k0 + kf * 4]);
    };
    auto storeB = [&](int buf) {
        int n = tid >> 2, kf = tid & 3;
        Bs[buf][(kf * 4 + 0) * 36 + n] = br.x;
        Bs[buf][(kf * 4 + 1) * 36 + n] = br.y;
        Bs[buf][(kf * 4 + 2) * 36 + n] = br.z;
        Bs[buf][(kf * 4 + 3) * 36 + n] = br.w;
    };

    loadA(0); loadB(0);
    storeA(0); storeB(0);
    __syncthreads();

    for (int kt = 0; kt < NT; ++kt) {
        int cur = kt & 1;
        if (kt + 1 < NT) { loadA((kt + 1) * 16); loadB((kt + 1) * 16); }
        #pragma unroll
        for (int kk = 0; kk < 16; ++kk) {
            float4 av = *reinterpret_cast<const float4*>(&As[cur][kk * 68 + tm * 4]);
            float4 bv = *reinterpret_cast<const float4*>(&Bs[cur][kk * 36 + tn * 4]);
            acc[0][0] += av.x * bv.x; acc[0][1] += av.x * bv.y;
            acc[0][2] += av.x * bv.z; acc[0][3] += av.x * bv.w;
            acc[1][0] += av.y * bv.x; acc[1][1] += av.y * bv.y;
            acc[1][2] += av.y * bv.z; acc[1][3] += av.y * bv.w;
            acc[2][0] += av.z * bv.x; acc[2][1] += av.z * bv.y;
            acc[2][2] += av.z * bv.z; acc[2][3] += av.z * bv.w;
            acc[3][0] += av.w * bv.x; acc[3][1] += av.w * bv.y;
            acc[3][2] += av.w * bv.z; acc[3][3] += av.w * bv.w;
        }
        if (kt + 1 < NT) { storeA(cur ^ 1); storeB(cur ^ 1); }
        __syncthreads();
    }

    #pragma unroll
    for (int i = 0; i < 4; i++) {
        int mg = m0 + tm * 4 + i;
        #pragma unroll
        for (int j = 0; j < 4; j++) {
            int ng = n0 + tn * 4 + j;
            g_hid[mg * kHid + ng] = fmaxf(acc[i][j] + b1[ng], 0.f);
        }
    }
}

// ---------------- head GEMM 2: (11520 x 256) @ (4 x 256)^T + bias -> output ----------------
__global__ void head2_kernel(const float* __restrict__ w2, const float* __restrict__ b2,
                             float* __restrict__ out) {
    int idx = blockIdx.x * 256 + threadIdx.x;      // 180 blocks -> 46080
    int m = idx >> 2, o = idx & 3;
    const float4* hp = reinterpret_cast<const float4*>(g_hid + m * kHid);
    const float4* wp = reinterpret_cast<const float4*>(w2 + o * kHid);
    float s = 0.f;
    #pragma unroll 8
    for (int k = 0; k < kHid / 4; k++) {
        float4 a = hp[k], b = wp[k];
        s += a.x * b.x + a.y * b.y + a.z * b.z + a.w * b.w;
    }
    s += b2[o];
    int bb = m & (kB - 1);
    int t  = m >> 7;
    out[bb * (kPred * kOut) + t * kOut + o] = s;   // (B, T_PRED, OUT)
}

// ---------------- launch ----------------
extern "C" void kernel_launch(void* const* d_in, const int* in_sizes, int n_in,
                              void* d_out, int out_size) {
    const float* ctx   = (const float*)d_in[0];
    const float* sx    = (const float*)d_in[1];
    const float* fut   = (const float*)d_in[2];
    const float* mlpw1 = (const float*)d_in[3];
    const float* mlpb1 = (const float*)d_in[4];
    const float* mlpw2 = (const float*)d_in[5];
    const float* mlpb2 = (const float*)d_in[6];
    const float* embw  = (const float*)d_in[7];
    const float* embb  = (const float*)d_in[8];
    const float* wih0  = (const float*)d_in[9];
    const float* whh0  = (const float*)d_in[10];
    const float* bih0  = (const float*)d_in[11];
    const float* bhh0  = (const float*)d_in[12];
    const float* wih1  = (const float*)d_in[13];
    const float* whh1  = (const float*)d_in[14];
    const float* bih1  = (const float*)d_in[15];
    const float* bhh1  = (const float*)d_in[16];
    const float* hw1   = (const float*)d_in[17];
    const float* hb1   = (const float*)d_in[18];
    const float* hw2   = (const float*)d_in[19];
    const float* hb2   = (const float*)d_in[20];
    float* out = (float*)d_out;

    // prep (once per graph; deterministic)
    prep_mlp1<<<kB, kMlp>>>(sx, mlpw1, mlpb1);
    prep_emb<<<kB, kEmb>>>(sx, embw, embb);
    prep_init<<<dim3(kB, 8), 256>>>(mlpw2, mlpb2);
    prep_pre0<<<dim3(kB, 8), 256>>>(wih0, bih0, bhh0);
    prep_pre1<<<8, 256>>>(bih1, bhh1);
    prep_W0<<<(kNG * kK0) / 256, 256>>>(whh0, wih0);
    prep_W1<<<(kNG * kK1) / 256, 256>>>(wih1, whh1);

    // sequential scan: 455 steps x 2 layers
    for (int t = 0; t < kT; t++) {
        int par = t & 1;
        const float* xp;
        int xs;
        if (t < kCtx) { xp = ctx + t * kDdyn;          xs = kCtx * kDdyn; }
        else          { xp = fut + (t - kCtx) * kDdyn; xs = kPred * kDdyn; }
        lstm_step<true ><<<dim3(2, 64), 128>>>(xp, xs, par, -1);
        lstm_step<false><<<dim3(2, 64), 128>>>(nullptr, 0, par, (t >= kCtx) ? (t - kCtx) : -1);
    }

    // batched output head over the 90 prediction steps
    head1_gemm<<<dim3(kM2 / 64, kHid / 32), 128>>>(hw1, hb1);
    head2_kernel<<<kM2 * kOut / 256, 256>>>(hw2, hb2, out);
}

// round 9
// speedup vs baseline: 1.0710x; 1.0710x over previous
#include <cuda_runtime.h>
#include <math.h>
#include <stdint.h>

// ---------------- problem constants ----------------
constexpr int kB    = 128;
constexpr int kH    = 512;
constexpr int kCtx  = 365;
constexpr int kPred = 90;
constexpr int kT    = 455;
constexpr int kDdyn = 10;
constexpr int kEmb  = 64;
constexpr int kStat = 36;
constexpr int kMlp  = 128;
constexpr int kOut  = 4;
constexpr int kNG   = 2048;          // 4*H gate rows (interleaved: n = unit*4 + gate)
constexpr int kKstr0 = 544;          // 512 h + 10 x + 22 pad  (34 chunks of 16)
constexpr int kKstr1 = 1024;         // 512 y0 + 512 h1        (64 chunks of 16)
constexpr int kNch0 = 34, kNch1 = 64;
constexpr int kKS0  = 2,  kKS1  = 4; // K-splits
constexpr int kHid  = 256;
constexpr int kM2   = kPred * kB;

// ---------------- device scratch ----------------
__device__ __align__(16) float g_W0h[kNG * kKstr0];
__device__ __align__(16) float g_W0l[kNG * kKstr0];
__device__ __align__(16) float g_W1h[kNG * kKstr1];
__device__ __align__(16) float g_W1l[kNG * kKstr1];
__device__ __align__(16) float g_pre0[kB * kNG];
__device__ __align__(16) float g_pre1[kNG];
__device__ __align__(16) float g_h0[2 * kB * kKstr0];     // [buf][B][544] = [h | x | pad0]
__device__ __align__(16) float g_in1[2 * kB * kKstr1];    // [buf][B][1024] = [y0 | h1]
__device__ __align__(16) float g_c0[kB * kH];
__device__ __align__(16) float g_c1[kB * kH];
__device__ __align__(16) float g_emb[kB * kEmb];
__device__ __align__(16) float g_mlp1[kB * kMlp];
__device__ __align__(16) float g_part0[32 * kKS0 * kB * 64];
__device__ __align__(16) float g_part1[32 * kKS1 * kB * 64];
__device__ int g_cnt0[32];
__device__ int g_cnt1[32];
__device__ __align__(16) float g_Y1[kM2 * kH];
__device__ __align__(16) float g_hid[kM2 * kHid];

__device__ __forceinline__ float sigm(float x) { return 1.f / (1.f + expf(-x)); }

__device__ __forceinline__ uint32_t f2tf(float x) {
    uint32_t r; asm("cvt.rna.tf32.f32 %0, %1;\n" : "=r"(r) : "f"(x)); return r;
}

__device__ __forceinline__ void mma8(float c[4], const uint32_t a[4], uint32_t b0, uint32_t b1) {
    asm volatile("mma.sync.aligned.m16n8k8.row.col.f32.tf32.tf32.f32 "
                 "{%0,%1,%2,%3},{%4,%5,%6,%7},{%8,%9},{%0,%1,%2,%3};\n"
                 : "+f"(c[0]), "+f"(c[1]), "+f"(c[2]), "+f"(c[3])
                 : "r"(a[0]), "r"(a[1]), "r"(a[2]), "r"(a[3]), "r"(b0), "r"(b1));
}

__device__ __forceinline__ void cpa16(void* sptr, const void* gptr) {
    uint32_t s = (uint32_t)__cvta_generic_to_shared(sptr);
    asm volatile("cp.async.ca.shared.global [%0], [%1], 16;\n" :: "r"(s), "l"(gptr));
}

// ---------------- prep kernels ----------------
__global__ void prep_mlp1(const float* __restrict__ sx, const float* __restrict__ w1,
                          const float* __restrict__ b1) {
    int b = blockIdx.x, m = threadIdx.x;
    float s = b1[m];
    #pragma unroll
    for (int d = 0; d < kStat; d++) s += sx[b * kStat + d] * w1[m * kStat + d];
    g_mlp1[b * kMlp + m] = fmaxf(s, 0.f);
}

__global__ void prep_emb(const float* __restrict__ sx, const float* __restrict__ ew,
                         const float* __restrict__ eb) {
    int b = blockIdx.x, e = threadIdx.x;
    float s = eb[e];
    #pragma unroll
    for (int d = 0; d < kStat; d++) s += sx[b * kStat + d] * ew[e * kStat + d];
    g_emb[b * kEmb + e] = fmaxf(s, 0.f);
}

__global__ void prep_init(const float* __restrict__ w2, const float* __restrict__ b2) {
    int b = blockIdx.x;
    int r = blockIdx.y * 256 + threadIdx.x;
    float s = b2[r];
    #pragma unroll 4
    for (int m = 0; m < kMlp; m++) s += g_mlp1[b * kMlp + m] * w2[r * kMlp + m];
    int ss = r >> 10, l = (r >> 9) & 1, h = r & 511;
    if (ss == 0) {
        if (l == 0) g_h0[b * kKstr0 + h] = s;                // buffer 0, h-part
        else        g_in1[b * kKstr1 + kH + h] = s;          // buffer 0, h1 half
    } else {
        if (l == 0) g_c0[b * kH + h] = s;
        else        g_c1[b * kH + h] = s;
    }
}

__global__ void prep_xpad(const float* __restrict__ ctx) {
    int b = blockIdx.x; int z = threadIdx.x;                 // 64 threads
    int buf = z >> 5, c = 512 + (z & 31);
    if (buf == 1 || c >= 512 + kDdyn + 12 - 12 + 10)         // keep simple below
        ;
    // zero pad columns (skip buf0 x-slots to avoid race with x write)
    if (buf == 1 || c >= 512 + kDdyn)
        g_h0[buf * kB * kKstr0 + b * kKstr0 + c] = 0.f;
    if (z < kDdyn)
        g_h0[b * kKstr0 + 512 + z] = ctx[b * (kCtx * kDdyn) + z];   // x at t=0
}

__global__ void prep_pre0(const float* __restrict__ wih0, const float* __restrict__ bih,
                          const float* __restrict__ bhh) {
    int b = blockIdx.x;
    int n = blockIdx.y * 256 + threadIdx.x;
    int j = (n & 3) * kH + (n >> 2);
    float s = bih[j] + bhh[j];
    #pragma unroll 8
    for (int e = 0; e < kEmb; e++)
        s += g_emb[b * kEmb + e] * wih0[j * (kDdyn + kEmb) + kDdyn + e];
    g_pre0[b * kNG + n] = s;
}

__global__ void prep_pre1(const float* __restrict__ bih, const float* __restrict__ bhh) {
    int n = blockIdx.x * 256 + threadIdx.x;
    int j = (n & 3) * kH + (n >> 2);
    g_pre1[n] = bih[j] + bhh[j];
}

__global__ void prep_W0(const float* __restrict__ whh0, const float* __restrict__ wih0) {
    int idx = blockIdx.x * 256 + threadIdx.x;        // 4352 blocks = 2048*544
    int n = idx / kKstr0, k = idx % kKstr0;
    int j = (n & 3) * kH + (n >> 2);
    float v = 0.f;
    if (k < kH)              v = whh0[j * kH + k];
    else if (k < kH + kDdyn) v = wih0[j * (kDdyn + kEmb) + (k - kH)];
    uint32_t hb = f2tf(v);
    g_W0h[idx] = __uint_as_float(hb);
    g_W0l[idx] = __uint_as_float(f2tf(v - __uint_as_float(hb)));
}

__global__ void prep_W1(const float* __restrict__ wih1, const float* __restrict__ whh1) {
    int idx = blockIdx.x * 256 + threadIdx.x;        // 8192 blocks = 2048*1024
    int n = idx >> 10, k = idx & 1023;
    int j = (n & 3) * kH + (n >> 2);
    float v = (k < kH) ? wih1[j * kH + k] : whh1[j * kH + (k - kH)];
    uint32_t hb = f2tf(v);
    g_W1h[idx] = __uint_as_float(hb);
    g_W1l[idx] = __uint_as_float(f2tf(v - __uint_as_float(hb)));
}

// ---------------- fused LSTM step: 3xTF32 MMA GEMM + K-split + in-kernel reduce/epilogue
// grid(32 n-tiles, KS), 256 threads. CTA tile: M=128 (full batch), N=64 (16 units).
template <int L>
__global__ void __launch_bounds__(256) lstm_mma(int par, const float* __restrict__ xnext,
                                                int xstride, int trow) {
    constexpr int KSTR = (L == 0) ? kKstr0 : kKstr1;
    constexpr int NCH  = (L == 0) ? kNch0  : kNch1;
    constexpr int KS   = (L == 0) ? kKS0   : kKS1;
    constexpr int CPK  = NCH / KS;                   // 17 / 16 chunks of 16

    const int tid = threadIdx.x;
    const int ntile = blockIdx.x;
    const int kz = blockIdx.y;
    const int n0 = ntile * 64;
    const int cbeg = kz * CPK;

    const float* __restrict__ A  = (L == 0 ? g_h0 : g_in1) + par * kB * KSTR;
    const float* __restrict__ Wh = (L == 0) ? g_W0h : g_W1h;
    const float* __restrict__ Wl = (L == 0) ? g_W0l : g_W1l;
    float* __restrict__ part = (L == 0) ? g_part0 : g_part1;
    int* __restrict__ cnt = (L == 0) ? g_cnt0 : g_cnt1;

    __shared__ __align__(16) float sm[10240];        // As[2][128][20] | Bh[2][64][20] | Bl[2][64][20]
    float* As = sm;                                  // 5120 floats
    float* Bh = sm + 5120;                           // 2560
    float* Bl = sm + 7680;                           // 2560
    __shared__ int sOld;

    // L0 side job: stage x_{t+1} into the other h0 buffer (not read this step)
    if (L == 0 && ntile == 0 && kz == 0 && xnext) {
        float* dst = g_h0 + (par ^ 1) * kB * kKstr0;
        for (int i = tid; i < kB * kDdyn; i += 256) {
            int m = i / kDdyn, d = i - m * kDdyn;
            dst[m * kKstr0 + 512 + d] = xnext[m * xstride + d];
        }
    }

    const int w = tid >> 5, lane = tid & 31;
    const int wm = w & 3, wn = w >> 2;               // warp grid 4(M) x 2(N)
    const int g = lane >> 2, t = lane & 3;

    float acc[2][4][4];
    #pragma unroll
    for (int a = 0; a < 2; a++)
        #pragma unroll
        for (int b = 0; b < 4; b++)
            #pragma unroll
            for (int c = 0; c < 4; c++) acc[a][b][c] = 0.f;

    auto stage = [&](int buf, int c) {
        int k0 = c * 16;
        #pragma unroll
        for (int r = 0; r < 2; r++) {
            int i = tid + 256 * r;
            int row = i >> 2, q = i & 3;
            cpa16(&As[buf * 2560 + row * 20 + q * 4], &A[row * KSTR + k0 + q * 4]);
        }
        {
            int n = tid >> 2, q = tid & 3;
            cpa16(&Bh[buf * 1280 + n * 20 + q * 4], &Wh[(n0 + n) * KSTR + k0 + q * 4]);
            cpa16(&Bl[buf * 1280 + n * 20 + q * 4], &Wl[(n0 + n) * KSTR + k0 + q * 4]);
        }
        asm volatile("cp.async.commit_group;\n");
    };

    auto compute = [&](int buf) {
        const float* Ab  = &As[buf * 2560];
        const float* Bhb = &Bh[buf * 1280];
        const float* Blb = &Bl[buf * 1280];
        #pragma unroll
        for (int kk = 0; kk < 16; kk += 8) {
            uint32_t ah[2][4], al[2][4];
            #pragma unroll
            for (int mf = 0; mf < 2; mf++) {
                #pragma unroll
                for (int e = 0; e < 4; e++) {
                    int row = wm * 32 + mf * 16 + g + (e & 1) * 8;
                    int col = kk + t + (e >> 1) * 4;
                    float v = Ab[row * 20 + col];
                    uint32_t h = f2tf(v);
                    ah[mf][e] = h;
                    al[mf][e] = f2tf(v - __uint_as_float(h));
                }
            }
            #pragma unroll
            for (int nf = 0; nf < 4; nf++) {
                int n = wn * 32 + nf * 8 + g;
                uint32_t bh0 = __float_as_uint(Bhb[n * 20 + kk + t]);
                uint32_t bh1 = __float_as_uint(Bhb[n * 20 + kk + t + 4]);
                uint32_t bl0 = __float_as_uint(Blb[n * 20 + kk + t]);
                uint32_t bl1 = __float_as_uint(Blb[n * 20 + kk + t + 4]);
                #pragma unroll
                for (int mf = 0; mf < 2; mf++) {
                    mma8(acc[mf][nf], ah[mf], bh0, bh1);
                    mma8(acc[mf][nf], ah[mf], bl0, bl1);
                    mma8(acc[mf][nf], al[mf], bh0, bh1);
                }
            }
        }
    };

    stage(0, cbeg);
    #pragma unroll 1
    for (int i = 0; i < CPK; i++) {
        int buf = i & 1;
        if (i + 1 < CPK) {
            stage(buf ^ 1, cbeg + i + 1);
            asm volatile("cp.async.wait_group 1;\n");
        } else {
            asm volatile("cp.async.wait_group 0;\n");
        }
        __syncthreads();
        compute(buf);
        __syncthreads();
    }

    // stage gate tile to SMEM (aliases operand buffers; all K-loop reads done)
    float* Gs = sm;                                  // [128][65]
    #pragma unroll
    for (int mf = 0; mf < 2; mf++)
        #pragma unroll
        for (int nf = 0; nf < 4; nf++) {
            int row = wm * 32 + mf * 16 + g;
            int col = wn * 32 + nf * 8 + t * 2;
            Gs[row * 65 + col]           = acc[mf][nf][0];
            Gs[row * 65 + col + 1]       = acc[mf][nf][1];
            Gs[(row + 8) * 65 + col]     = acc[mf][nf][2];
            Gs[(row + 8) * 65 + col + 1] = acc[mf][nf][3];
        }
    __syncthreads();

    const int m = tid >> 1;
    const int nh = (tid & 1) * 32;
    {
        float* pp = &part[(size_t)((ntile * KS + kz) * kB + m) * 64 + nh];
        #pragma unroll
        for (int j = 0; j < 32; j += 4) {
            float4 v = make_float4(Gs[m * 65 + nh + j],     Gs[m * 65 + nh + j + 1],
                                   Gs[m * 65 + nh + j + 2], Gs[m * 65 + nh + j + 3]);
            *reinterpret_cast<float4*>(pp + j) = v;
        }
    }
    __threadfence();
    __syncthreads();
    if (tid == 0) sOld = atomicAdd(&cnt[ntile], 1);
    __syncthreads();
    if (sOld != KS - 1) return;
    if (tid == 0) cnt[ntile] = 0;                    // rearm for next step / replay

    // reduce K-splits (fixed order -> deterministic), then fused gate epilogue
    float s[32];
    #pragma unroll
    for (int j = 0; j < 32; j++) s[j] = 0.f;
    #pragma unroll 1
    for (int z = 0; z < KS; z++) {
        const float4* q = reinterpret_cast<const float4*>(
            &part[(size_t)((ntile * KS + z) * kB + m) * 64 + nh]);
        #pragma unroll
        for (int j = 0; j < 8; j++) {
            float4 v = __ldcg(q + j);
            s[j * 4]     += v.x; s[j * 4 + 1] += v.y;
            s[j * 4 + 2] += v.z; s[j * 4 + 3] += v.w;
        }
    }

    const float* pre = (L == 0) ? &g_pre0[m * kNG + n0 + nh] : &g_pre1[n0 + nh];
    float* __restrict__ cst = (L == 0) ? g_c0 : g_c1;
    #pragma unroll
    for (int j = 0; j < 32; j += 4) {
        int u = (n0 + nh + j) >> 2;
        float gi = s[j]     + pre[j];
        float gf = s[j + 1] + pre[j + 1];
        float gg = s[j + 2] + pre[j + 2];
        float go = s[j + 3] + pre[j + 3];
        float iv = sigm(gi), fv = sigm(gf), gv = tanhf(gg), ov = sigm(go);
        float c = fv * cst[m * kH + u] + iv * gv;
        cst[m * kH + u] = c;
        float h = ov * tanhf(c);
        if (L == 0) {
            g_h0[(par ^ 1) * kB * kKstr0 + m * kKstr0 + u] = h;   // next-step h0
            g_in1[par * kB * kKstr1 + m * kKstr1 + u] = h;        // y0 for this step's L1
        } else {
            g_in1[(par ^ 1) * kB * kKstr1 + m * kKstr1 + kH + u] = h;  // next-step h1
            if (trow >= 0) g_Y1[(size_t)(trow * kB + m) * kH + u] = h;
        }
    }
}

// ---------------- head GEMM 1: (11520 x 512) @ (256 x 512)^T + bias, relu ----------------
__global__ void __launch_bounds__(128) head1_gemm(const float* __restrict__ w1,
                                                  const float* __restrict__ b1) {
    __shared__ __align__(16) float As[2][16 * 68];
    __shared__ __align__(16) float Bs[2][16 * 36];
    const int tid = threadIdx.x;
    const int m0 = blockIdx.x * 64, n0 = blockIdx.y * 32;
    const int tm = tid & 15, tn = tid >> 4;
    constexpr int Ks = kH, NT = Ks / 16;

    float acc[4][4];
    #pragma unroll
    for (int i = 0; i < 4; i++)
        #pragma unroll
        for (int j = 0; j < 4; j++) acc[i][j] = 0.f;

    float ar[8];
    float4 br;

    auto loadA = [&](int k0) {
        #pragma unroll
        for (int i = 0; i < 2; i++) {
            int li = tid * 2 + i;
            int bb = li >> 2, kf = li & 3;
            float4 v = *reinterpret_cast<const float4*>(&g_Y1[(m0 + bb) * kH + k0 + kf * 4]);
            ar[i * 4 + 0] = v.x; ar[i * 4 + 1] = v.y; ar[i * 4 + 2] = v.z; ar[i * 4 + 3] = v.w;
        }
    };
    auto storeA = [&](int buf) {
        #pragma unroll
        for (int i = 0; i < 2; i++) {
            int li = tid * 2 + i;
            int bb = li >> 2, kf = li & 3;
            #pragma unroll
            for (int j = 0; j < 4; j++) As[buf][(kf * 4 + j) * 68 + bb] = ar[i * 4 + j];
        }
    };
    auto loadB = [&](int k0) {
        int n = tid >> 2, kf = tid & 3;
        br = *reinterpret_cast<const float4*>(&w1[(n0 + n) * Ks + k0 + kf * 4]);
    };
    auto storeB = [&](int buf) {
        int n = tid >> 2, kf = tid & 3;
        Bs[buf][(kf * 4 + 0) * 36 + n] = br.x;
        Bs[buf][(kf * 4 + 1) * 36 + n] = br.y;
        Bs[buf][(kf * 4 + 2) * 36 + n] = br.z;
        Bs[buf][(kf * 4 + 3) * 36 + n] = br.w;
    };

    loadA(0); loadB(0);
    storeA(0); storeB(0);
    __syncthreads();

    for (int kt = 0; kt < NT; ++kt) {
        int cur = kt & 1;
        if (kt + 1 < NT) { loadA((kt + 1) * 16); loadB((kt + 1) * 16); }
        #pragma unroll
        for (int kk = 0; kk < 16; ++kk) {
            float4 av = *reinterpret_cast<const float4*>(&As[cur][kk * 68 + tm * 4]);
            float4 bv = *reinterpret_cast<const float4*>(&Bs[cur][kk * 36 + tn * 4]);
            acc[0][0] += av.x * bv.x; acc[0][1] += av.x * bv.y;
            acc[0][2] += av.x * bv.z; acc[0][3] += av.x * bv.w;
            acc[1][0] += av.y * bv.x; acc[1][1] += av.y * bv.y;
            acc[1][2] += av.y * bv.z; acc[1][3] += av.y * bv.w;
            acc[2][0] += av.z * bv.x; acc[2][1] += av.z * bv.y;
            acc[2][2] += av.z * bv.z; acc[2][3] += av.z * bv.w;
            acc[3][0] += av.w * bv.x; acc[3][1] += av.w * bv.y;
            acc[3][2] += av.w * bv.z; acc[3][3] += av.w * bv.w;
        }
        if (kt + 1 < NT) { storeA(cur ^ 1); storeB(cur ^ 1); }
        __syncthreads();
    }

    #pragma unroll
    for (int i = 0; i < 4; i++) {
        int mg = m0 + tm * 4 + i;
        #pragma unroll
        for (int j = 0; j < 4; j++) {
            int ng = n0 + tn * 4 + j;
            g_hid[mg * kHid + ng] = fmaxf(acc[i][j] + b1[ng], 0.f);
        }
    }
}

// ---------------- head GEMM 2: (11520 x 256) @ (4 x 256)^T + bias -> output ----------------
__global__ void head2_kernel(const float* __restrict__ w2, const float* __restrict__ b2,
                             float* __restrict__ out) {
    int idx = blockIdx.x * 256 + threadIdx.x;
    int m = idx >> 2, o = idx & 3;
    const float4* hp = reinterpret_cast<const float4*>(g_hid + m * kHid);
    const float4* wp = reinterpret_cast<const float4*>(w2 + o * kHid);
    float s = 0.f;
    #pragma unroll 8
    for (int k = 0; k < kHid / 4; k++) {
        float4 a = hp[k], b = wp[k];
        s += a.x * b.x + a.y * b.y + a.z * b.z + a.w * b.w;
    }
    s += b2[o];
    int bb = m & (kB - 1);
    int t  = m >> 7;
    out[bb * (kPred * kOut) + t * kOut + o] = s;
}

// ---------------- launch ----------------
extern "C" void kernel_launch(void* const* d_in, const int* in_sizes, int n_in,
                              void* d_out, int out_size) {
    const float* ctx   = (const float*)d_in[0];
    const float* sx    = (const float*)d_in[1];
    const float* fut   = (const float*)d_in[2];
    const float* mlpw1 = (const float*)d_in[3];
    const float* mlpb1 = (const float*)d_in[4];
    const float* mlpw2 = (const float*)d_in[5];
    const float* mlpb2 = (const float*)d_in[6];
    const float* embw  = (const float*)d_in[7];
    const float* embb  = (const float*)d_in[8];
    const float* wih0  = (const float*)d_in[9];
    const float* wih0b = wih0;
    const float* whh0  = (const float*)d_in[10];
    const float* bih0  = (const float*)d_in[11];
    const float* bhh0  = (const float*)d_in[12];
    const float* wih1  = (const float*)d_in[13];
    const float* whh1  = (const float*)d_in[14];
    const float* bih1  = (const float*)d_in[15];
    const float* bhh1  = (const float*)d_in[16];
    const float* hw1   = (const float*)d_in[17];
    const float* hb1   = (const float*)d_in[18];
    const float* hw2   = (const float*)d_in[19];
    const float* hb2   = (const float*)d_in[20];
    float* out = (float*)d_out;
    (void)wih0b;

    // prep (deterministic; runs inside the graph each replay)
    prep_mlp1<<<kB, kMlp>>>(sx, mlpw1, mlpb1);
    prep_emb<<<kB, kEmb>>>(sx, embw, embb);
    prep_init<<<dim3(kB, 8), 256>>>(mlpw2, mlpb2);
    prep_xpad<<<kB, 64>>>(ctx);
    prep_pre0<<<dim3(kB, 8), 256>>>(wih0, bih0, bhh0);
    prep_pre1<<<8, 256>>>(bih1, bhh1);
    prep_W0<<<(kNG * kKstr0) / 256, 256>>>(whh0, wih0);
    prep_W1<<<(kNG * kKstr1) / 256, 256>>>(wih1, whh1);

    // sequential scan: 455 steps x 2 layers (tensor-core GEMMs, fused epilogue)
    for (int t = 0; t < kT; t++) {
        int par = t & 1;
        const float* xn = nullptr;
        int xs = 0;
        int tn = t + 1;
        if (tn < kCtx)      { xn = ctx + tn * kDdyn;          xs = kCtx * kDdyn; }
        else if (tn < kT)   { xn = fut + (tn - kCtx) * kDdyn; xs = kPred * kDdyn; }
        lstm_mma<0><<<dim3(32, kKS0), 256>>>(par, xn, xs, -1);
        lstm_mma<1><<<dim3(32, kKS1), 256>>>(par, nullptr, 0, (t >= kCtx) ? (t - kCtx) : -1);
    }

    // batched output head over the 90 prediction steps
    head1_gemm<<<dim3(kM2 / 64, kHid / 32), 128>>>(hw1, hb1);
    head2_kernel<<<kM2 * kOut / 256, 256>>>(hw2, hb2, out);
}